// round 1
// baseline (speedup 1.0000x reference)
#include <cuda_runtime.h>

// Problem constants (fixed by the dataset)
#define NN 100000
#define EE 1600000

// Scratch (device globals — no allocation allowed)
__device__ float g_deg [NN];
__device__ float g_agg1[NN * 64];   // sum_{j->i} x_j           (layer 1, 64-wide)
__device__ float g_h   [NN * 128];  // relu(sageconv1)          (128-wide)
__device__ float g_p   [NN * 64];   // h @ W2_l^T               (projected BEFORE aggregation)
__device__ float g_hr  [NN * 64];   // h @ W2_r^T + b2
__device__ float g_agg2[NN * 64];   // sum_{j->i} p_j

__device__ __forceinline__ void red4(float* a, float4 v) {
    asm volatile("red.global.add.v4.f32 [%0], {%1,%2,%3,%4};"
                 :: "l"(a), "f"(v.x), "f"(v.y), "f"(v.z), "f"(v.w) : "memory");
}
__device__ __forceinline__ void red1(float* a, float v) {
    asm volatile("red.global.add.f32 [%0], %1;" :: "l"(a), "f"(v) : "memory");
}

// ---------------------------------------------------------------- zero
__global__ void k_zero() {
    int i = blockIdx.x * blockDim.x + threadIdx.x;
    if (i < NN * 16) {
        ((float4*)g_agg1)[i] = make_float4(0.f, 0.f, 0.f, 0.f);
        ((float4*)g_agg2)[i] = make_float4(0.f, 0.f, 0.f, 0.f);
    }
    if (i < NN) g_deg[i] = 0.f;
}

// ---------------------------------------------------------------- edge pass 1: agg1 += x[src], deg += 1
__global__ void k_edge1(const int* __restrict__ ei, const float* __restrict__ x) {
    long long idx = (long long)blockIdx.x * blockDim.x + threadIdx.x;
    int e = (int)(idx >> 4);
    if (e >= EE) return;
    int lane = (int)(idx & 15);
    int s = __ldg(ei + e);
    int d = __ldg(ei + EE + e);
    float4 v = __ldg(((const float4*)x) + (long long)s * 16 + lane);
    red4(g_agg1 + (long long)d * 64 + lane * 4, v);
    if (lane == 0) red1(g_deg + d, 1.f);
}

// ---------------------------------------------------------------- edge pass 2: agg2 += p[src]
__global__ void k_edge2(const int* __restrict__ ei) {
    long long idx = (long long)blockIdx.x * blockDim.x + threadIdx.x;
    int e = (int)(idx >> 4);
    if (e >= EE) return;
    int lane = (int)(idx & 15);
    int s = __ldg(ei + e);
    int d = __ldg(ei + EE + e);
    float4 v = __ldg(((const float4*)g_p) + (long long)s * 16 + lane);
    red4(g_agg2 + (long long)d * 64 + lane * 4, v);
}

// ---------------------------------------------------------------- GEMM layer 1
// h = relu( Wcat[128 x 128] @ [agg1/deg ; x]  + b1 ),   Wcat = [W1_l | W1_r]
// Tile: 64 nodes x 128 ch per block, 256 threads, 8x4 register tile.
#define WPAD 132
__global__ void k_node1(const float* __restrict__ x,
                        const float* __restrict__ W1l,
                        const float* __restrict__ W1r,
                        const float* __restrict__ b1) {
    extern __shared__ float sm[];
    float* w_sh = sm;                 // [k=128][oc padded to 132]
    float* a_sh = sm + 128 * WPAD;    // [node=64][k=128]
    float* b_sh = a_sh + 64 * 128;    // [128]
    int t = threadIdx.x;

    for (int idx = t; idx < 128 * 128; idx += 256) {
        int oc = idx >> 7, k = idx & 127;
        float v = (k < 64) ? W1l[oc * 64 + k] : W1r[oc * 64 + (k - 64)];
        w_sh[k * WPAD + oc] = v;
    }
    if (t < 128) b_sh[t] = b1[t];

    int base = blockIdx.x * 64;
    for (int idx = t; idx < 64 * 128; idx += 256) {
        int node = idx >> 7, k = idx & 127;
        int n = base + node;
        float v = 0.f;
        if (n < NN) {
            if (k < 64) {
                float inv = 1.f / fmaxf(g_deg[n], 1.f);
                v = g_agg1[(long long)n * 64 + k] * inv;
            } else {
                v = x[(long long)n * 64 + (k - 64)];
            }
        }
        a_sh[node * 128 + k] = v;
    }
    __syncthreads();

    int cg = t & 31, ng = t >> 5;
    int ch4 = cg * 4;
    float acc[8][4];
#pragma unroll
    for (int i = 0; i < 8; i++)
#pragma unroll
        for (int j = 0; j < 4; j++) acc[i][j] = 0.f;

    const float* a_base = a_sh + (ng * 8) * 128;
#pragma unroll 4
    for (int k = 0; k < 128; k++) {
        float4 w4 = *(const float4*)(w_sh + k * WPAD + ch4);
#pragma unroll
        for (int i = 0; i < 8; i++) {
            float av = a_base[i * 128 + k];
            acc[i][0] += av * w4.x;
            acc[i][1] += av * w4.y;
            acc[i][2] += av * w4.z;
            acc[i][3] += av * w4.w;
        }
    }

#pragma unroll
    for (int i = 0; i < 8; i++) {
        int n = base + ng * 8 + i;
        if (n < NN) {
            float4 o;
            o.x = fmaxf(acc[i][0] + b_sh[ch4 + 0], 0.f);
            o.y = fmaxf(acc[i][1] + b_sh[ch4 + 1], 0.f);
            o.z = fmaxf(acc[i][2] + b_sh[ch4 + 2], 0.f);
            o.w = fmaxf(acc[i][3] + b_sh[ch4 + 3], 0.f);
            *(float4*)(g_h + (long long)n * 128 + ch4) = o;
        }
    }
}

// ---------------------------------------------------------------- GEMM layer 2 (fused W2_l / W2_r):
// [p ; hr] = h @ [W2_l ; W2_r]^T ,  hr gets +b2.  oc<64 -> p, oc>=64 -> hr.
__global__ void k_gemm2(const float* __restrict__ W2l,
                        const float* __restrict__ W2r,
                        const float* __restrict__ b2) {
    extern __shared__ float sm[];
    float* w_sh = sm;                 // [k=128][oc padded 132]
    float* a_sh = sm + 128 * WPAD;    // [node=64][k=128]
    float* b_sh = a_sh + 64 * 128;    // [64]
    int t = threadIdx.x;

    for (int idx = t; idx < 128 * 128; idx += 256) {
        int oc = idx >> 7, k = idx & 127;
        float v = (oc < 64) ? W2l[oc * 128 + k] : W2r[(oc - 64) * 128 + k];
        w_sh[k * WPAD + oc] = v;
    }
    if (t < 64) b_sh[t] = b2[t];

    int base = blockIdx.x * 64;
    for (int idx = t; idx < 64 * 128; idx += 256) {
        int node = idx >> 7, k = idx & 127;
        int n = base + node;
        a_sh[node * 128 + k] = (n < NN) ? g_h[(long long)n * 128 + k] : 0.f;
    }
    __syncthreads();

    int cg = t & 31, ng = t >> 5;
    int ch4 = cg * 4;
    float acc[8][4];
#pragma unroll
    for (int i = 0; i < 8; i++)
#pragma unroll
        for (int j = 0; j < 4; j++) acc[i][j] = 0.f;

    const float* a_base = a_sh + (ng * 8) * 128;
#pragma unroll 4
    for (int k = 0; k < 128; k++) {
        float4 w4 = *(const float4*)(w_sh + k * WPAD + ch4);
#pragma unroll
        for (int i = 0; i < 8; i++) {
            float av = a_base[i * 128 + k];
            acc[i][0] += av * w4.x;
            acc[i][1] += av * w4.y;
            acc[i][2] += av * w4.z;
            acc[i][3] += av * w4.w;
        }
    }

#pragma unroll
    for (int i = 0; i < 8; i++) {
        int n = base + ng * 8 + i;
        if (n < NN) {
            if (ch4 < 64) {   // -> p
                float4 o = make_float4(acc[i][0], acc[i][1], acc[i][2], acc[i][3]);
                *(float4*)(g_p + (long long)n * 64 + ch4) = o;
            } else {          // -> hr (+b2)
                int c = ch4 - 64;
                float4 o;
                o.x = acc[i][0] + b_sh[c + 0];
                o.y = acc[i][1] + b_sh[c + 1];
                o.z = acc[i][2] + b_sh[c + 2];
                o.w = acc[i][3] + b_sh[c + 3];
                *(float4*)(g_hr + (long long)n * 64 + c) = o;
            }
        }
    }
}

// ---------------------------------------------------------------- epilogue: out = sigmoid(agg2/deg + hr)
__global__ void k_out(float* __restrict__ out) {
    int i = blockIdx.x * blockDim.x + threadIdx.x;
    if (i >= NN * 16) return;
    int n = i >> 4;
    float inv = 1.f / fmaxf(g_deg[n], 1.f);
    float4 a = ((const float4*)g_agg2)[i];
    float4 r = ((const float4*)g_hr)[i];
    float4 o;
    o.x = 1.f / (1.f + __expf(-(a.x * inv + r.x)));
    o.y = 1.f / (1.f + __expf(-(a.y * inv + r.y)));
    o.z = 1.f / (1.f + __expf(-(a.z * inv + r.z)));
    o.w = 1.f / (1.f + __expf(-(a.w * inv + r.w)));
    ((float4*)out)[i] = o;
}

// ----------------------------------------------------------------
extern "C" void kernel_launch(void* const* d_in, const int* in_sizes, int n_in,
                              void* d_out, int out_size) {
    const float* x   = (const float*)d_in[0];
    const int*   ei  = (const int*)  d_in[1];
    const float* W1l = (const float*)d_in[2];
    const float* W1r = (const float*)d_in[3];
    const float* b1  = (const float*)d_in[4];
    const float* W2l = (const float*)d_in[5];
    const float* W2r = (const float*)d_in[6];
    const float* b2  = (const float*)d_in[7];
    float* out = (float*)d_out;

    const int SMEM1 = (128 * WPAD + 64 * 128 + 128) * 4;
    const int SMEM2 = (128 * WPAD + 64 * 128 + 64) * 4;
    cudaFuncSetAttribute(k_node1, cudaFuncAttributeMaxDynamicSharedMemorySize, SMEM1);
    cudaFuncSetAttribute(k_gemm2, cudaFuncAttributeMaxDynamicSharedMemorySize, SMEM2);

    int zgrid = (NN * 16 + 255) / 256;
    int egrid = (int)(((long long)EE * 16 + 255) / 256);
    int ggrid = (NN + 63) / 64;

    k_zero <<<zgrid, 256>>>();
    k_edge1<<<egrid, 256>>>(ei, x);
    k_node1<<<ggrid, 256, SMEM1>>>(x, W1l, W1r, b1);
    k_gemm2<<<ggrid, 256, SMEM2>>>(W2l, W2r, b2);
    k_edge2<<<egrid, 256>>>(ei);
    k_out  <<<zgrid, 256>>>(out);
}